// round 16
// baseline (speedup 1.0000x reference)
#include <cuda_runtime.h>
#include <math.h>
#include <stdint.h>

#define BATCH 64
#define NN    512
#define HH    256
#define DNODE 38
#define TOKENS (BATCH*NN)
#define NTILE (TOKENS/32)      // 1024 lidar tiles, 16 per batch

// ---------------- scratch (device globals) ----------------------------------
__device__ float g_node[(size_t)TOKENS * DNODE];
__device__ float g_S0part[NTILE][DNODE];
__device__ unsigned g_farmask[(size_t)TOKENS * 16];
__device__ int g_ndH[128];                       // per far-half-block dirty count
__device__ unsigned short g_dirtyJH[128][256];   // per far-half-block dirty j list
__device__ int g_slot[TOKENS];                   // -1 clean (memset 0xFF)

// ---------------- K1: far detect (blocks 0..127) + lidar (128..1151) ---------
union SmemK1 {
    struct { float lidT[20][36]; float hidS[32 * 256]; float nodeb[32][38]; } L; // ~39.6KB
    struct { float px[NN]; float py[NN]; int wcnt[8]; } F;
};

__global__ __launch_bounds__(256)
void k1_kernel(const float* __restrict__ data,
               const float* __restrict__ lw1, const float* __restrict__ lb1,
               const float* __restrict__ lw2, const float* __restrict__ lb2)
{
    __shared__ SmemK1 sm;
    int tid = threadIdx.x, w = tid >> 5, lane = tid & 31;

    if (blockIdx.x >= 128) {
        // ================= lidar MLP tile (32 tokens) =================
        int tok0 = (blockIdx.x - 128) * 32;
        float* stage = sm.L.hidS;                   // scratch for lw1 staging
        for (int idx = tid; idx < 20 * 256; idx += 256) stage[idx] = lw1[idx];
        for (int idx = tid; idx < 20 * 32; idx += 256) {
            int c = idx >> 5, t = idx & 31;
            sm.L.lidT[c][t] = data[(size_t)(tok0 + t) * DNODE + 18 + c];
        }
        for (int idx = tid; idx < 32 * 18; idx += 256) {
            int t = idx / 18, c = idx % 18;
            sm.L.nodeb[t][c] = data[(size_t)(tok0 + t) * DNODE + c];
        }
        __syncthreads();
        float wreg[20];
        #pragma unroll
        for (int k = 0; k < 20; k++) wreg[k] = stage[tid * 20 + k];
        float b1v = lb1[tid];
        __syncthreads();          // wreg read done; hidS may be overwritten

        // layer 1: hid(t, h=tid), 4 tokens per LDS.128 broadcast.
        // store into hidS with chunk-XOR swizzle: (t,h) -> t*256 + ((h/4 ^ (t&7))*4 + h%4
        int chunk = tid >> 2, jj = tid & 3;
        #pragma unroll
        for (int tg = 0; tg < 8; tg++) {
            float a0 = b1v, a1 = b1v, a2 = b1v, a3 = b1v;
            #pragma unroll
            for (int k = 0; k < 20; k++) {
                float4 lv = *(const float4*)&sm.L.lidT[k][tg * 4];
                a0 += wreg[k] * lv.x; a1 += wreg[k] * lv.y;
                a2 += wreg[k] * lv.z; a3 += wreg[k] * lv.w;
            }
            int t0 = tg * 4;
            sm.L.hidS[(t0 + 0) * 256 + ((chunk ^ ((t0 + 0) & 7)) << 2) + jj] = fmaxf(a0, 0.f);
            sm.L.hidS[(t0 + 1) * 256 + ((chunk ^ ((t0 + 1) & 7)) << 2) + jj] = fmaxf(a1, 0.f);
            sm.L.hidS[(t0 + 2) * 256 + ((chunk ^ ((t0 + 2) & 7)) << 2) + jj] = fmaxf(a2, 0.f);
            sm.L.hidS[(t0 + 3) * 256 + ((chunk ^ ((t0 + 3) & 7)) << 2) + jj] = fmaxf(a3, 0.f);
        }
        __syncthreads();

        // layer 2: warp w -> outputs {w, w+8, w+16}, lane = token t.
        // NO shuffles: lane t accumulates out[t][o] over swizzled hid row + broadcast w row.
        {
            int t = lane;
            const float4* hid4 = (const float4*)(sm.L.hidS + t * 256);
            int sw = t & 7;
            #pragma unroll
            for (int oi = 0; oi < 3; oi++) {
                int o = w + oi * 8;
                if (o < 20) {
                    const float4* w4 = (const float4*)(lw2 + o * 256);
                    float a0 = 0.f, a1 = 0.f, a2 = 0.f, a3 = 0.f;
                    #pragma unroll
                    for (int c = 0; c < 64; c++) {
                        float4 hv = hid4[c ^ sw];
                        float4 wv = w4[c];
                        a0 += hv.x * wv.x; a1 += hv.y * wv.y;
                        a2 += hv.z * wv.z; a3 += hv.w * wv.w;
                    }
                    float s = (a0 + a1) + (a2 + a3);
                    sm.L.nodeb[t][18 + o] = fmaxf(s + lb2[o], 0.f);
                }
            }
        }
        __syncthreads();

        for (int idx = tid; idx < 32 * 38; idx += 256) {
            int t = idx / 38, c = idx % 38;
            g_node[(size_t)(tok0 + t) * DNODE + c] = sm.L.nodeb[t][c];
        }
        if (tid < DNODE) {
            float s = 0.f;
            #pragma unroll 8
            for (int t = 0; t < 32; t++) s += sm.L.nodeb[t][tid];
            g_S0part[blockIdx.x - 128][tid] = s;
        }
    } else {
        // ================= far-pair detect (2 half-blocks per batch) =========
        int fb = blockIdx.x;
        int b = fb >> 1, half = fb & 1;
        const float* db = data + (size_t)b * NN * DNODE;
        for (int i = tid; i < NN; i += 256) {
            sm.F.px[i] = db[(size_t)i * DNODE + 0];
            sm.F.py[i] = db[(size_t)i * DNODE + 1];
        }
        __syncthreads();
        unsigned short myj[32];
        int mycnt = 0;
        int j0 = half * 256 + w * 32;
        for (int jj2 = 0; jj2 < 32; jj2++) {
            int j = j0 + jj2;
            float xj = sm.F.px[j], yj = sm.F.py[j];
            unsigned mm[16], any = 0;
            #pragma unroll
            for (int wd = 0; wd < 16; wd++) {
                int i = wd * 32 + lane;
                float dx = sm.F.px[i] - xj, dy = sm.F.py[i] - yj;
                float d2 = dx * dx + dy * dy;
                bool near_ = d2 <= 100.0f;
                if (d2 > 99.0f && d2 < 101.0f) near_ = (sqrtf(d2) <= 10.0f);
                bool far = (i != j) && !near_;
                mm[wd] = __ballot_sync(~0u, far);
                any |= mm[wd];
            }
            if (any) {
                if (!lane) {
                    #pragma unroll
                    for (int wd = 0; wd < 16; wd++)
                        g_farmask[((size_t)(b * NN + j)) * 16 + wd] = mm[wd];
                    myj[mycnt] = (unsigned short)j;
                    g_slot[b * NN + j] = 1;
                }
                mycnt++;
            }
        }
        if (!lane) sm.F.wcnt[w] = mycnt;
        __syncthreads();
        if (tid == 0) {
            int tot = 0;
            #pragma unroll
            for (int q = 0; q < 8; q++) tot += sm.F.wcnt[q];
            g_ndH[fb] = tot;
        }
        if (!lane && mycnt) {
            int off = 0;
            for (int q = 0; q < w; q++) off += sm.F.wcnt[q];
            for (int k = 0; k < mycnt; k++)
                g_dirtyJH[fb][off + k] = myj[k];
        }
    }
}

// ---------------- helpers -----------------------------------------------------
__device__ __forceinline__ int nd_total() {
    int a = 0;
    for (int h = 0; h < 128; h++) a += g_ndH[h];
    return a;
}
__device__ __forceinline__ int find_dirty(int e, int& b) {
    int acc = 0;
    for (int h = 0; h < 128; h++) {
        int c = g_ndH[h];
        if (e < acc + c) { b = h >> 1; return b * NN + g_dirtyJH[h][e - acc]; }
        acc += c;
    }
    return 0;
}
__device__ __forceinline__ bool is_far(int tok, int jloc) {
    return (g_farmask[(size_t)tok * 16 + (jloc >> 5)] >> (jloc & 31)) & 1u;
}

// ---------------- K2: GIN1 + S1 + GIN2 + transformer + head + scatter --------
// 512 threads = 16 warps; each GEMV warp computes 16 outputs.
__global__ __launch_bounds__(512)
void rest_kernel(const float* __restrict__ g1w1, const float* __restrict__ g1b1,
                 const float* __restrict__ g1w2, const float* __restrict__ g1b2,
                 const float* __restrict__ g2w1, const float* __restrict__ g2b1,
                 const float* __restrict__ g2w2, const float* __restrict__ g2b2,
                 const float* __restrict__ t_in_w, const float* __restrict__ t_in_b,
                 const float* __restrict__ t_out_w, const float* __restrict__ t_out_b,
                 const float* __restrict__ t_ln1_g, const float* __restrict__ t_ln1_b,
                 const float* __restrict__ t_ff1_w, const float* __restrict__ t_ff1_b,
                 const float* __restrict__ t_ff2_w, const float* __restrict__ t_ff2_b,
                 const float* __restrict__ t_ln2_g, const float* __restrict__ t_ln2_b,
                 const float* __restrict__ fc_w, const float* __restrict__ fc_b,
                 float* __restrict__ out)
{
    __shared__ __align__(16) float X[256], T1[256], T2[256], ACC[256], SUB[256];
    __shared__ __align__(16) float x38[40];
    __shared__ float red[16];
    __shared__ float out5[5];
    int tid = threadIdx.x, w = tid >> 5, lane = tid & 31;

    auto gemv = [&](const float* src, float* dst, const float* W,
                    const float* bias, bool relu) {
        const float4* s4 = (const float4*)src;
        float4 xa = s4[lane], xb = s4[lane + 32];
        #pragma unroll 4
        for (int oo = 0; oo < 16; oo++) {
            int o = (w << 4) + oo;
            const float4* wr = (const float4*)(W + (size_t)o * HH);
            float4 wa = wr[lane], wb = wr[lane + 32];
            float s = wa.x * xa.x + wa.y * xa.y + wa.z * xa.z + wa.w * xa.w
                    + wb.x * xb.x + wb.y * xb.y + wb.z * xb.z + wb.w * xb.w;
            #pragma unroll
            for (int off = 16; off; off >>= 1) s += __shfl_xor_sync(~0u, s, off);
            if (!lane) {
                float a = s + bias[o];
                dst[o] = relu ? fmaxf(a, 0.f) : a;
            }
        }
        __syncthreads();
    };
    auto ln_row = [&](float* xv, const float* yv, const float* gg, const float* bb) {
        float v = 0.f, d = 0.f;
        if (tid < 256) {
            v = xv[tid] + yv[tid];
            float s = v;
            #pragma unroll
            for (int off = 16; off; off >>= 1) s += __shfl_xor_sync(~0u, s, off);
            if (!lane) red[w] = s;
        }
        __syncthreads();
        if (tid < 256) {
            float tot = 0.f;
            #pragma unroll
            for (int q = 0; q < 8; q++) tot += red[q];
            d = v - tot * (1.0f / 256.0f);
            float s2 = d * d;
            #pragma unroll
            for (int off = 16; off; off >>= 1) s2 += __shfl_xor_sync(~0u, s2, off);
            if (!lane) red[8 + w] = s2;
        }
        __syncthreads();
        if (tid < 256) {
            float tot2 = 0.f;
            #pragma unroll
            for (int q = 0; q < 8; q++) tot2 += red[8 + q];
            float var = tot2 * (1.0f / 256.0f);
            xv[tid] = d / sqrtf(var + 1e-5f) * gg[tid] + bb[tid];
        }
        __syncthreads();
    };
    auto build_x38 = [&](int b, int tok) {
        if (tid < DNODE) {
            float v = 0.f;
            #pragma unroll
            for (int p = 0; p < 16; p++) v += g_S0part[b * 16 + p][tid];
            if (tok >= 0) {
                for (int wd = 0; wd < 16; wd++) {
                    unsigned m = g_farmask[(size_t)tok * 16 + wd];
                    while (m) {
                        int i = wd * 32 + __ffs(m) - 1; m &= m - 1;
                        v -= g_node[((size_t)b * NN + i) * DNODE + tid];
                    }
                }
            }
            x38[tid] = v;
        }
        __syncthreads();
    };
    auto gin1_chain = [&](float* dst) {
        {
            float xa = x38[lane];
            float xb = (lane < 6) ? x38[32 + lane] : 0.f;
            #pragma unroll 4
            for (int oo = 0; oo < 16; oo++) {
                int o = (w << 4) + oo;
                const float* wr = g1w1 + o * DNODE;
                float s = wr[lane] * xa;
                if (lane < 6) s += wr[32 + lane] * xb;
                #pragma unroll
                for (int off = 16; off; off >>= 1) s += __shfl_xor_sync(~0u, s, off);
                if (!lane) T1[o] = fmaxf(s + g1b1[o], 0.0f);
            }
        }
        __syncthreads();
        gemv(T1, dst, g1w2, g1b2, true);
    };
    auto chain_tail = [&]() {
        gemv(X, T1, g2w1, g2b1, true);
        gemv(T1, X, g2w2, g2b2, true);
        #pragma unroll 1
        for (int l = 0; l < 2; l++) {
            const float* Wv  = t_in_w + (size_t)l * 768 * HH + (size_t)512 * HH;
            const float* bv  = t_in_b + (size_t)l * 768 + 512;
            const float* Wo  = t_out_w + (size_t)l * HH * HH;
            const float* bo  = t_out_b + (size_t)l * HH;
            const float* W1  = t_ff1_w + (size_t)l * HH * HH;
            const float* b1  = t_ff1_b + (size_t)l * HH;
            const float* W2  = t_ff2_w + (size_t)l * HH * HH;
            const float* b2  = t_ff2_b + (size_t)l * HH;
            gemv(X,  T1, Wv, bv, false);
            gemv(T1, T2, Wo, bo, false);
            ln_row(X, T2, t_ln1_g + (size_t)l * HH, t_ln1_b + (size_t)l * HH);
            gemv(X,  T1, W1, b1, true);
            gemv(T1, T2, W2, b2, false);
            ln_row(X, T2, t_ln2_g + (size_t)l * HH, t_ln2_b + (size_t)l * HH);
        }
        if (w < 5) {
            const float* wr = fc_w + w * HH;
            float s = 0.f;
            #pragma unroll
            for (int q = 0; q < 8; q++) s += X[lane + 32 * q] * wr[lane + 32 * q];
            #pragma unroll
            for (int off = 16; off; off >>= 1) s += __shfl_xor_sync(~0u, s, off);
            if (!lane) out5[w] = s + fc_b[w];
        }
        __syncthreads();
    };
    auto accumulate_S1 = [&](int b, int nd, int reftok) {
        if (tid < 256) {
            ACC[tid] = (float)(NN - nd) * X[tid];
            SUB[tid] = 0.f;
        }
        __syncthreads();
        if (nd) {
            for (int h = 2 * b; h <= 2 * b + 1; h++) {
                int c = g_ndH[h];
                for (int k = 0; k < c; k++) {
                    int jloc = g_dirtyJH[h][k];
                    int tok2 = b * NN + jloc;
                    build_x38(b, tok2);
                    gin1_chain(T2);
                    if (tid < 256) {
                        float t = T2[tid];
                        ACC[tid] += t;
                        if (reftok >= 0 && is_far(reftok, jloc)) SUB[tid] += t;
                    }
                    __syncthreads();
                }
            }
        }
    };

    if (blockIdx.x < 64) {
        int b = blockIdx.x;
        build_x38(b, -1);
        gin1_chain(X);                               // X = uniform h1
        int nd = g_ndH[2 * b] + g_ndH[2 * b + 1];
        accumulate_S1(b, nd, -1);
        if (tid < 256) X[tid] = ACC[tid];
        __syncthreads();
        chain_tail();
        for (int t = tid; t < NN; t += 512) {
            int tk = b * NN + t;
            if (g_slot[tk] < 0) {
                float* o = out + (size_t)tk * 5;
                o[0] = out5[0]; o[1] = out5[1]; o[2] = out5[2];
                o[3] = out5[3]; o[4] = out5[4];
            }
        }
    } else {
        __shared__ int s_nD;
        if (tid == 0) s_nD = nd_total();
        __syncthreads();
        int nD = s_nD;
        for (int e = blockIdx.x - 64; e < nD; e += 64) {
            int b;
            int tok = find_dirty(e, b);
            build_x38(b, -1);
            gin1_chain(X);                           // uniform h1
            int nd = g_ndH[2 * b] + g_ndH[2 * b + 1];
            accumulate_S1(b, nd, tok);
            if (tid < 256) X[tid] = ACC[tid] - SUB[tid];
            __syncthreads();
            chain_tail();
            if (tid < 5) out[(size_t)tok * 5 + tid] = out5[tid];
            __syncthreads();
        }
    }
}

// ---------------- launch ------------------------------------------------------
extern "C" void kernel_launch(void* const* d_in, const int* in_sizes, int n_in,
                              void* d_out, int out_size)
{
    const float* data   = (const float*)d_in[0];
    const float* lw1    = (const float*)d_in[1];
    const float* lb1    = (const float*)d_in[2];
    const float* lw2    = (const float*)d_in[3];
    const float* lb2    = (const float*)d_in[4];
    const float* g1w1   = (const float*)d_in[5];
    const float* g1b1   = (const float*)d_in[6];
    const float* g1w2   = (const float*)d_in[7];
    const float* g1b2   = (const float*)d_in[8];
    const float* g2w1   = (const float*)d_in[9];
    const float* g2b1   = (const float*)d_in[10];
    const float* g2w2   = (const float*)d_in[11];
    const float* g2b2   = (const float*)d_in[12];
    const float* t_in_w = (const float*)d_in[13];
    const float* t_in_b = (const float*)d_in[14];
    const float* t_out_w= (const float*)d_in[15];
    const float* t_out_b= (const float*)d_in[16];
    const float* t_ln1_g= (const float*)d_in[17];
    const float* t_ln1_b= (const float*)d_in[18];
    const float* t_ff1_w= (const float*)d_in[19];
    const float* t_ff1_b= (const float*)d_in[20];
    const float* t_ff2_w= (const float*)d_in[21];
    const float* t_ff2_b= (const float*)d_in[22];
    const float* t_ln2_g= (const float*)d_in[23];
    const float* t_ln2_b= (const float*)d_in[24];
    const float* fc_w   = (const float*)d_in[25];
    const float* fc_b   = (const float*)d_in[26];
    float* out = (float*)d_out;

    void* slotp;
    cudaGetSymbolAddress(&slotp, g_slot);
    cudaMemsetAsync(slotp, 0xFF, sizeof(int) * TOKENS);   // all clean (-1)

    k1_kernel<<<NTILE + 128, 256>>>(data, lw1, lb1, lw2, lb2);
    rest_kernel<<<128, 512>>>(g1w1, g1b1, g1w2, g1b2,
                              g2w1, g2b1, g2w2, g2b2,
                              t_in_w, t_in_b, t_out_w, t_out_b,
                              t_ln1_g, t_ln1_b, t_ff1_w, t_ff1_b,
                              t_ff2_w, t_ff2_b, t_ln2_g, t_ln2_b,
                              fc_w, fc_b, out);
    (void)in_sizes; (void)n_in; (void)out_size;
}

// round 17
// speedup vs baseline: 1.4054x; 1.4054x over previous
#include <cuda_runtime.h>
#include <math.h>
#include <stdint.h>

#define BATCH 64
#define NN    512
#define HH    256
#define DNODE 38
#define TOKENS (BATCH*NN)
#define NTILE (TOKENS/32)      // 1024 lidar tiles, 16 per batch

// ---------------- scratch (device globals) ----------------------------------
__device__ float g_node[(size_t)TOKENS * DNODE];
__device__ float g_S0part[NTILE][DNODE];
__device__ unsigned g_farmask[(size_t)TOKENS * 16];
__device__ int g_ndH[128];                       // per far-half-block dirty count
__device__ unsigned short g_dirtyJH[128][256];   // per far-half-block dirty j list
__device__ int g_slot[TOKENS];                   // -1 clean (memset 0xFF)

// ---------------- K1: far detect (blocks 0..127) + lidar (128..1151) ---------
union SmemK1 {
    struct { float lidT[20][36]; float hid[32][260]; float nodeb[32][38]; } L;  // ~41KB
    struct { float px[NN]; float py[NN]; int wcnt[8]; } F;
};

__global__ __launch_bounds__(256)
void k1_kernel(const float* __restrict__ data,
               const float* __restrict__ lw1, const float* __restrict__ lb1,
               const float* __restrict__ lw2, const float* __restrict__ lb2)
{
    __shared__ SmemK1 sm;
    int tid = threadIdx.x, w = tid >> 5, lane = tid & 31;

    if (blockIdx.x >= 128) {
        // ================= lidar MLP tile (32 tokens) =================
        int tok0 = (blockIdx.x - 128) * 32;
        for (int idx = tid; idx < 20 * 32; idx += 256) {
            int c = idx >> 5, t = idx & 31;
            sm.L.lidT[c][t] = data[(size_t)(tok0 + t) * DNODE + 18 + c];
        }
        for (int idx = tid; idx < 32 * 18; idx += 256) {
            int t = idx / 18, c = idx % 18;
            sm.L.nodeb[t][c] = data[(size_t)(tok0 + t) * DNODE + c];
        }
        float wreg[20];
        #pragma unroll
        for (int k = 0; k < 20; k++) wreg[k] = lw1[tid * 20 + k];
        float b1v = lb1[tid];
        __syncthreads();

        // layer 1: hid[t][tid], 4 tokens per LDS.128 broadcast
        #pragma unroll
        for (int tg = 0; tg < 8; tg++) {
            float a0 = b1v, a1 = b1v, a2 = b1v, a3 = b1v;
            #pragma unroll
            for (int k = 0; k < 20; k++) {
                float4 lv = *(const float4*)&sm.L.lidT[k][tg * 4];
                a0 += wreg[k] * lv.x; a1 += wreg[k] * lv.y;
                a2 += wreg[k] * lv.z; a3 += wreg[k] * lv.w;
            }
            sm.L.hid[tg * 4 + 0][tid] = fmaxf(a0, 0.f);
            sm.L.hid[tg * 4 + 1][tid] = fmaxf(a1, 0.f);
            sm.L.hid[tg * 4 + 2][tid] = fmaxf(a2, 0.f);
            sm.L.hid[tg * 4 + 3][tid] = fmaxf(a3, 0.f);
        }
        __syncthreads();

        // layer 2: warp w owns tokens 4w..4w+3; hid in regs, weights loaded
        // once per output and reused across the 4 tokens.
        {
            int t0 = w * 4;
            float h[4][8];
            #pragma unroll
            for (int tt = 0; tt < 4; tt++)
                #pragma unroll
                for (int q = 0; q < 8; q++)
                    h[tt][q] = sm.L.hid[t0 + tt][lane + 32 * q];
            for (int o = 0; o < 20; o++) {
                const float* wr = lw2 + o * 256;
                float wv[8];
                #pragma unroll
                for (int q = 0; q < 8; q++) wv[q] = wr[lane + 32 * q];
                #pragma unroll
                for (int tt = 0; tt < 4; tt++) {
                    float s = 0.f;
                    #pragma unroll
                    for (int q = 0; q < 8; q++) s += wv[q] * h[tt][q];
                    #pragma unroll
                    for (int off = 16; off; off >>= 1) s += __shfl_xor_sync(~0u, s, off);
                    if (!lane) sm.L.nodeb[t0 + tt][18 + o] = fmaxf(s + lb2[o], 0.f);
                }
            }
        }
        __syncthreads();

        for (int idx = tid; idx < 32 * 38; idx += 256) {
            int t = idx / 38, c = idx % 38;
            g_node[(size_t)(tok0 + t) * DNODE + c] = sm.L.nodeb[t][c];
        }
        if (tid < DNODE) {
            float s = 0.f;
            #pragma unroll 8
            for (int t = 0; t < 32; t++) s += sm.L.nodeb[t][tid];
            g_S0part[blockIdx.x - 128][tid] = s;
        }
    } else {
        // ================= far-pair detect (2 half-blocks per batch) =========
        int fb = blockIdx.x;
        int b = fb >> 1, half = fb & 1;
        const float* db = data + (size_t)b * NN * DNODE;
        for (int i = tid; i < NN; i += 256) {
            sm.F.px[i] = db[(size_t)i * DNODE + 0];
            sm.F.py[i] = db[(size_t)i * DNODE + 1];
        }
        __syncthreads();
        unsigned short myj[32];
        int mycnt = 0;
        int j0 = half * 256 + w * 32;
        for (int jj = 0; jj < 32; jj++) {
            int j = j0 + jj;
            float xj = sm.F.px[j], yj = sm.F.py[j];
            unsigned mm[16], any = 0;
            #pragma unroll
            for (int wd = 0; wd < 16; wd++) {
                int i = wd * 32 + lane;
                float dx = sm.F.px[i] - xj, dy = sm.F.py[i] - yj;
                float d2 = dx * dx + dy * dy;
                bool near_ = d2 <= 100.0f;
                if (d2 > 99.0f && d2 < 101.0f) near_ = (sqrtf(d2) <= 10.0f);
                bool far = (i != j) && !near_;
                mm[wd] = __ballot_sync(~0u, far);
                any |= mm[wd];
            }
            if (any) {
                if (!lane) {
                    #pragma unroll
                    for (int wd = 0; wd < 16; wd++)
                        g_farmask[((size_t)(b * NN + j)) * 16 + wd] = mm[wd];
                    myj[mycnt] = (unsigned short)j;
                    g_slot[b * NN + j] = 1;
                }
                mycnt++;
            }
        }
        if (!lane) sm.F.wcnt[w] = mycnt;
        __syncthreads();
        if (tid == 0) {
            int tot = 0;
            #pragma unroll
            for (int q = 0; q < 8; q++) tot += sm.F.wcnt[q];
            g_ndH[fb] = tot;
        }
        if (!lane && mycnt) {
            int off = 0;
            for (int q = 0; q < w; q++) off += sm.F.wcnt[q];
            for (int k = 0; k < mycnt; k++)
                g_dirtyJH[fb][off + k] = myj[k];
        }
    }
}

// ---------------- helpers -----------------------------------------------------
__device__ __forceinline__ int nd_total() {
    int a = 0;
    for (int h = 0; h < 128; h++) a += g_ndH[h];
    return a;
}
__device__ __forceinline__ int find_dirty(int e, int& b) {
    int acc = 0;
    for (int h = 0; h < 128; h++) {
        int c = g_ndH[h];
        if (e < acc + c) { b = h >> 1; return b * NN + g_dirtyJH[h][e - acc]; }
        acc += c;
    }
    return 0;
}
__device__ __forceinline__ bool is_far(int tok, int jloc) {
    return (g_farmask[(size_t)tok * 16 + (jloc >> 5)] >> (jloc & 31)) & 1u;
}

// ---------------- K2: GIN1 + S1 + GIN2 + transformer + head + scatter --------
// 512 threads = 16 warps; each GEMV warp computes 16 outputs.
__global__ __launch_bounds__(512)
void rest_kernel(const float* __restrict__ g1w1, const float* __restrict__ g1b1,
                 const float* __restrict__ g1w2, const float* __restrict__ g1b2,
                 const float* __restrict__ g2w1, const float* __restrict__ g2b1,
                 const float* __restrict__ g2w2, const float* __restrict__ g2b2,
                 const float* __restrict__ t_in_w, const float* __restrict__ t_in_b,
                 const float* __restrict__ t_out_w, const float* __restrict__ t_out_b,
                 const float* __restrict__ t_ln1_g, const float* __restrict__ t_ln1_b,
                 const float* __restrict__ t_ff1_w, const float* __restrict__ t_ff1_b,
                 const float* __restrict__ t_ff2_w, const float* __restrict__ t_ff2_b,
                 const float* __restrict__ t_ln2_g, const float* __restrict__ t_ln2_b,
                 const float* __restrict__ fc_w, const float* __restrict__ fc_b,
                 float* __restrict__ out)
{
    __shared__ __align__(16) float X[256], T1[256], T2[256], ACC[256], SUB[256];
    __shared__ __align__(16) float x38[40];
    __shared__ float red[16];
    __shared__ float out5[5];
    int tid = threadIdx.x, w = tid >> 5, lane = tid & 31;

    auto gemv = [&](const float* src, float* dst, const float* W,
                    const float* bias, bool relu) {
        const float4* s4 = (const float4*)src;
        float4 xa = s4[lane], xb = s4[lane + 32];
        #pragma unroll 4
        for (int oo = 0; oo < 16; oo++) {
            int o = (w << 4) + oo;
            const float4* wr = (const float4*)(W + (size_t)o * HH);
            float4 wa = wr[lane], wb = wr[lane + 32];
            float s = wa.x * xa.x + wa.y * xa.y + wa.z * xa.z + wa.w * xa.w
                    + wb.x * xb.x + wb.y * xb.y + wb.z * xb.z + wb.w * xb.w;
            #pragma unroll
            for (int off = 16; off; off >>= 1) s += __shfl_xor_sync(~0u, s, off);
            if (!lane) {
                float a = s + bias[o];
                dst[o] = relu ? fmaxf(a, 0.f) : a;
            }
        }
        __syncthreads();
    };
    auto ln_row = [&](float* xv, const float* yv, const float* gg, const float* bb) {
        float v = 0.f, d = 0.f;
        if (tid < 256) {
            v = xv[tid] + yv[tid];
            float s = v;
            #pragma unroll
            for (int off = 16; off; off >>= 1) s += __shfl_xor_sync(~0u, s, off);
            if (!lane) red[w] = s;
        }
        __syncthreads();
        if (tid < 256) {
            float tot = 0.f;
            #pragma unroll
            for (int q = 0; q < 8; q++) tot += red[q];
            d = v - tot * (1.0f / 256.0f);
            float s2 = d * d;
            #pragma unroll
            for (int off = 16; off; off >>= 1) s2 += __shfl_xor_sync(~0u, s2, off);
            if (!lane) red[8 + w] = s2;
        }
        __syncthreads();
        if (tid < 256) {
            float tot2 = 0.f;
            #pragma unroll
            for (int q = 0; q < 8; q++) tot2 += red[8 + q];
            float var = tot2 * (1.0f / 256.0f);
            xv[tid] = d / sqrtf(var + 1e-5f) * gg[tid] + bb[tid];
        }
        __syncthreads();
    };
    auto build_x38 = [&](int b, int tok) {
        if (tid < DNODE) {
            float v = 0.f;
            #pragma unroll
            for (int p = 0; p < 16; p++) v += g_S0part[b * 16 + p][tid];
            if (tok >= 0) {
                for (int wd = 0; wd < 16; wd++) {
                    unsigned m = g_farmask[(size_t)tok * 16 + wd];
                    while (m) {
                        int i = wd * 32 + __ffs(m) - 1; m &= m - 1;
                        v -= g_node[((size_t)b * NN + i) * DNODE + tid];
                    }
                }
            }
            x38[tid] = v;
        }
        __syncthreads();
    };
    auto gin1_chain = [&](float* dst) {
        {
            float xa = x38[lane];
            float xb = (lane < 6) ? x38[32 + lane] : 0.f;
            #pragma unroll 4
            for (int oo = 0; oo < 16; oo++) {
                int o = (w << 4) + oo;
                const float* wr = g1w1 + o * DNODE;
                float s = wr[lane] * xa;
                if (lane < 6) s += wr[32 + lane] * xb;
                #pragma unroll
                for (int off = 16; off; off >>= 1) s += __shfl_xor_sync(~0u, s, off);
                if (!lane) T1[o] = fmaxf(s + g1b1[o], 0.0f);
            }
        }
        __syncthreads();
        gemv(T1, dst, g1w2, g1b2, true);
    };
    auto chain_tail = [&]() {
        gemv(X, T1, g2w1, g2b1, true);
        gemv(T1, X, g2w2, g2b2, true);
        #pragma unroll 1
        for (int l = 0; l < 2; l++) {
            const float* Wv  = t_in_w + (size_t)l * 768 * HH + (size_t)512 * HH;
            const float* bv  = t_in_b + (size_t)l * 768 + 512;
            const float* Wo  = t_out_w + (size_t)l * HH * HH;
            const float* bo  = t_out_b + (size_t)l * HH;
            const float* W1  = t_ff1_w + (size_t)l * HH * HH;
            const float* b1  = t_ff1_b + (size_t)l * HH;
            const float* W2  = t_ff2_w + (size_t)l * HH * HH;
            const float* b2  = t_ff2_b + (size_t)l * HH;
            gemv(X,  T1, Wv, bv, false);
            gemv(T1, T2, Wo, bo, false);
            ln_row(X, T2, t_ln1_g + (size_t)l * HH, t_ln1_b + (size_t)l * HH);
            gemv(X,  T1, W1, b1, true);
            gemv(T1, T2, W2, b2, false);
            ln_row(X, T2, t_ln2_g + (size_t)l * HH, t_ln2_b + (size_t)l * HH);
        }
        if (w < 5) {
            const float* wr = fc_w + w * HH;
            float s = 0.f;
            #pragma unroll
            for (int q = 0; q < 8; q++) s += X[lane + 32 * q] * wr[lane + 32 * q];
            #pragma unroll
            for (int off = 16; off; off >>= 1) s += __shfl_xor_sync(~0u, s, off);
            if (!lane) out5[w] = s + fc_b[w];
        }
        __syncthreads();
    };
    auto accumulate_S1 = [&](int b, int nd, int reftok) {
        if (tid < 256) {
            ACC[tid] = (float)(NN - nd) * X[tid];
            SUB[tid] = 0.f;
        }
        __syncthreads();
        if (nd) {
            for (int h = 2 * b; h <= 2 * b + 1; h++) {
                int c = g_ndH[h];
                for (int k = 0; k < c; k++) {
                    int jloc = g_dirtyJH[h][k];
                    int tok2 = b * NN + jloc;
                    build_x38(b, tok2);
                    gin1_chain(T2);
                    if (tid < 256) {
                        float t = T2[tid];
                        ACC[tid] += t;
                        if (reftok >= 0 && is_far(reftok, jloc)) SUB[tid] += t;
                    }
                    __syncthreads();
                }
            }
        }
    };

    if (blockIdx.x < 64) {
        int b = blockIdx.x;
        build_x38(b, -1);
        gin1_chain(X);                               // X = uniform h1
        int nd = g_ndH[2 * b] + g_ndH[2 * b + 1];
        accumulate_S1(b, nd, -1);
        if (tid < 256) X[tid] = ACC[tid];
        __syncthreads();
        chain_tail();
        for (int t = tid; t < NN; t += 512) {
            int tk = b * NN + t;
            if (g_slot[tk] < 0) {
                float* o = out + (size_t)tk * 5;
                o[0] = out5[0]; o[1] = out5[1]; o[2] = out5[2];
                o[3] = out5[3]; o[4] = out5[4];
            }
        }
    } else {
        __shared__ int s_nD;
        if (tid == 0) s_nD = nd_total();
        __syncthreads();
        int nD = s_nD;
        for (int e = blockIdx.x - 64; e < nD; e += 64) {
            int b;
            int tok = find_dirty(e, b);
            build_x38(b, -1);
            gin1_chain(X);                           // uniform h1
            int nd = g_ndH[2 * b] + g_ndH[2 * b + 1];
            accumulate_S1(b, nd, tok);
            if (tid < 256) X[tid] = ACC[tid] - SUB[tid];
            __syncthreads();
            chain_tail();
            if (tid < 5) out[(size_t)tok * 5 + tid] = out5[tid];
            __syncthreads();
        }
    }
}

// ---------------- launch ------------------------------------------------------
extern "C" void kernel_launch(void* const* d_in, const int* in_sizes, int n_in,
                              void* d_out, int out_size)
{
    const float* data   = (const float*)d_in[0];
    const float* lw1    = (const float*)d_in[1];
    const float* lb1    = (const float*)d_in[2];
    const float* lw2    = (const float*)d_in[3];
    const float* lb2    = (const float*)d_in[4];
    const float* g1w1   = (const float*)d_in[5];
    const float* g1b1   = (const float*)d_in[6];
    const float* g1w2   = (const float*)d_in[7];
    const float* g1b2   = (const float*)d_in[8];
    const float* g2w1   = (const float*)d_in[9];
    const float* g2b1   = (const float*)d_in[10];
    const float* g2w2   = (const float*)d_in[11];
    const float* g2b2   = (const float*)d_in[12];
    const float* t_in_w = (const float*)d_in[13];
    const float* t_in_b = (const float*)d_in[14];
    const float* t_out_w= (const float*)d_in[15];
    const float* t_out_b= (const float*)d_in[16];
    const float* t_ln1_g= (const float*)d_in[17];
    const float* t_ln1_b= (const float*)d_in[18];
    const float* t_ff1_w= (const float*)d_in[19];
    const float* t_ff1_b= (const float*)d_in[20];
    const float* t_ff2_w= (const float*)d_in[21];
    const float* t_ff2_b= (const float*)d_in[22];
    const float* t_ln2_g= (const float*)d_in[23];
    const float* t_ln2_b= (const float*)d_in[24];
    const float* fc_w   = (const float*)d_in[25];
    const float* fc_b   = (const float*)d_in[26];
    float* out = (float*)d_out;

    void* slotp;
    cudaGetSymbolAddress(&slotp, g_slot);
    cudaMemsetAsync(slotp, 0xFF, sizeof(int) * TOKENS);   // all clean (-1)

    k1_kernel<<<NTILE + 128, 256>>>(data, lw1, lb1, lw2, lb2);
    rest_kernel<<<128, 512>>>(g1w1, g1b1, g1w2, g1b2,
                              g2w1, g2b1, g2w2, g2b2,
                              t_in_w, t_in_b, t_out_w, t_out_b,
                              t_ln1_g, t_ln1_b, t_ff1_w, t_ff1_b,
                              t_ff2_w, t_ff2_b, t_ln2_g, t_ln2_b,
                              fc_w, fc_b, out);
    (void)in_sizes; (void)n_in; (void)out_size;
}